// round 1
// baseline (speedup 1.0000x reference)
#include <cuda_runtime.h>
#include <math.h>

#define H 4
#define Bb 8
#define Nn 1024
#define INF_ 1024
#define E 256
#define A_ 64
#define BN_ROWS 8192        /* B*N */
#define ALPHA 0.2f
#define NEGV -9e15f

// ---- scratch (static device memory; no runtime allocation) ----
__device__ float g_Wh[H * BN_ROWS * E];                 // 32 MB   [h][row][e]
__device__ float g_f1[H * BN_ROWS];
__device__ float g_f2[H * BN_ROWS];
__device__ float g_att[(size_t)H * Bb * Nn * Nn];       // 134 MB  [h][b][i][j]
__device__ float g_feat[(size_t)BN_ROWS * H * E];       // 32 MB   [row][h*E+e]

// ============================================================
// K1: Wh[h] (8192 x 256) = x (8192 x 1024) @ W[h] (1024 x 256)
// tile 128x64x16, 256 threads, 8x4 per thread
// ============================================================
__global__ void wh_gemm(const float* __restrict__ x, const float* __restrict__ W) {
    const int BM = 128, BNc = 64, BK = 16;
    __shared__ float As[BK][BM];
    __shared__ float Bs[BK][BNc];
    int h = blockIdx.z;
    int rowBase = blockIdx.y * BM;
    int colBase = blockIdx.x * BNc;
    const float* Bp = W + (size_t)h * INF_ * E;
    int tid = threadIdx.x;
    int tx = tid & 15, ty = tid >> 4;
    float acc[8][4] = {};
    for (int k0 = 0; k0 < INF_; k0 += BK) {
#pragma unroll
        for (int l = 0; l < 2; l++) {
            int f = tid + l * 256;
            int r = f >> 2, c4 = f & 3;
            float4 v = *(const float4*)(x + (size_t)(rowBase + r) * INF_ + k0 + c4 * 4);
            As[c4 * 4 + 0][r] = v.x;
            As[c4 * 4 + 1][r] = v.y;
            As[c4 * 4 + 2][r] = v.z;
            As[c4 * 4 + 3][r] = v.w;
        }
        {
            int r = tid >> 4, c4 = tid & 15;
            float4 v = *(const float4*)(Bp + (size_t)(k0 + r) * E + colBase + c4 * 4);
            *(float4*)&Bs[r][c4 * 4] = v;
        }
        __syncthreads();
#pragma unroll
        for (int kk = 0; kk < BK; kk++) {
            float a[8], b[4];
#pragma unroll
            for (int i = 0; i < 8; i++) a[i] = As[kk][ty * 8 + i];
            float4 bv = *(float4*)&Bs[kk][tx * 4];
            b[0] = bv.x; b[1] = bv.y; b[2] = bv.z; b[3] = bv.w;
#pragma unroll
            for (int i = 0; i < 8; i++)
#pragma unroll
                for (int j = 0; j < 4; j++) acc[i][j] += a[i] * b[j];
        }
        __syncthreads();
    }
    float* Cp = g_Wh + (size_t)h * BN_ROWS * E;
#pragma unroll
    for (int i = 0; i < 8; i++) {
        int r = rowBase + ty * 8 + i;
        float4 v = make_float4(acc[i][0], acc[i][1], acc[i][2], acc[i][3]);
        *(float4*)(Cp + (size_t)r * E + colBase + tx * 4) = v;
    }
}

// ============================================================
// K2: f1[h,row] = Wh[h,row,:] . a1[h,:], same for f2
// one 256-thread block per (h,row)
// ============================================================
__global__ void compute_f(const float* __restrict__ a1, const float* __restrict__ a2) {
    int r = blockIdx.x;                 // 0 .. H*BN_ROWS-1
    int h = r / BN_ROWS;
    int t = threadIdx.x;
    float v = g_Wh[(size_t)r * E + t];
    float s1 = v * a1[h * E + t];
    float s2 = v * a2[h * E + t];
#pragma unroll
    for (int o = 16; o > 0; o >>= 1) {
        s1 += __shfl_xor_sync(0xffffffffu, s1, o);
        s2 += __shfl_xor_sync(0xffffffffu, s2, o);
    }
    __shared__ float r1[8], r2[8];
    if ((t & 31) == 0) { r1[t >> 5] = s1; r2[t >> 5] = s2; }
    __syncthreads();
    if (t == 0) {
        float a = 0.f, b = 0.f;
#pragma unroll
        for (int i = 0; i < 8; i++) { a += r1[i]; b += r2[i]; }
        g_f1[r] = a;
        g_f2[r] = b;
    }
}

// ============================================================
// K3: att[h,b,i,:] = softmax_j( mask(leakyrelu(f1_i + f2_j)) )
// one 256-thread block per (h,b,i); 4 j's per thread in registers
// ============================================================
__global__ void softmax_att(const int* __restrict__ adj) {
    int i = blockIdx.x, b = blockIdx.y, h = blockIdx.z;
    int t = threadIdx.x;
    float f1v = g_f1[h * BN_ROWS + b * Nn + i];
    const int* adjrow = adj + ((size_t)b * Nn + i) * Nn;
    const float* f2p = g_f2 + h * BN_ROWS + b * Nn;

    float ev[4];
    float mx = -INFINITY;
#pragma unroll
    for (int l = 0; l < 4; l++) {
        int j = t + l * 256;
        float e = f1v + f2p[j];
        e = e > 0.f ? e : ALPHA * e;
        e = adjrow[j] > 0 ? e : NEGV;
        ev[l] = e;
        mx = fmaxf(mx, e);
    }
    __shared__ float sm[8];
    __shared__ float bc;
#pragma unroll
    for (int o = 16; o > 0; o >>= 1) mx = fmaxf(mx, __shfl_xor_sync(0xffffffffu, mx, o));
    if ((t & 31) == 0) sm[t >> 5] = mx;
    __syncthreads();
    if (t == 0) {
        float m = sm[0];
#pragma unroll
        for (int k = 1; k < 8; k++) m = fmaxf(m, sm[k]);
        bc = m;
    }
    __syncthreads();
    mx = bc;
    __syncthreads();

    float sum = 0.f;
    float ex[4];
#pragma unroll
    for (int l = 0; l < 4; l++) {
        ex[l] = __expf(ev[l] - mx);
        sum += ex[l];
    }
#pragma unroll
    for (int o = 16; o > 0; o >>= 1) sum += __shfl_xor_sync(0xffffffffu, sum, o);
    if ((t & 31) == 0) sm[t >> 5] = sum;
    __syncthreads();
    if (t == 0) {
        float s = 0.f;
#pragma unroll
        for (int k = 0; k < 8; k++) s += sm[k];
        bc = 1.f / s;
    }
    __syncthreads();
    float inv = bc;

    float* arow = g_att + (((size_t)(h * Bb + b)) * Nn + i) * Nn;
#pragma unroll
    for (int l = 0; l < 4; l++) arow[t + l * 256] = ex[l] * inv;
}

// ============================================================
// K4: h' = att(1024x1024) @ Wh_b(1024x256), elu, write transposed to feat
// grid (E/64, Nn/128, H*Bb)
// ============================================================
__global__ void att_gemm() {
    const int BM = 128, BNc = 64, BK = 16;
    __shared__ float As[BK][BM];
    __shared__ float Bs[BK][BNc];
    int hb = blockIdx.z;
    int h = hb / Bb, b = hb % Bb;
    int rowBase = blockIdx.y * BM;
    int colBase = blockIdx.x * BNc;
    const float* Ap = g_att + (size_t)hb * Nn * Nn;
    const float* Bp = g_Wh + ((size_t)h * BN_ROWS + b * Nn) * E;
    int tid = threadIdx.x;
    int tx = tid & 15, ty = tid >> 4;
    float acc[8][4] = {};
    for (int k0 = 0; k0 < Nn; k0 += BK) {
#pragma unroll
        for (int l = 0; l < 2; l++) {
            int f = tid + l * 256;
            int r = f >> 2, c4 = f & 3;
            float4 v = *(const float4*)(Ap + (size_t)(rowBase + r) * Nn + k0 + c4 * 4);
            As[c4 * 4 + 0][r] = v.x;
            As[c4 * 4 + 1][r] = v.y;
            As[c4 * 4 + 2][r] = v.z;
            As[c4 * 4 + 3][r] = v.w;
        }
        {
            int r = tid >> 4, c4 = tid & 15;
            float4 v = *(const float4*)(Bp + (size_t)(k0 + r) * E + colBase + c4 * 4);
            *(float4*)&Bs[r][c4 * 4] = v;
        }
        __syncthreads();
#pragma unroll
        for (int kk = 0; kk < BK; kk++) {
            float a[8], bv2[4];
#pragma unroll
            for (int i = 0; i < 8; i++) a[i] = As[kk][ty * 8 + i];
            float4 bv = *(float4*)&Bs[kk][tx * 4];
            bv2[0] = bv.x; bv2[1] = bv.y; bv2[2] = bv.z; bv2[3] = bv.w;
#pragma unroll
            for (int i = 0; i < 8; i++)
#pragma unroll
                for (int j = 0; j < 4; j++) acc[i][j] += a[i] * bv2[j];
        }
        __syncthreads();
    }
    // epilogue: elu, write to feat[(b*Nn + r)][h*E + col]
#pragma unroll
    for (int i = 0; i < 8; i++) {
        int r = rowBase + ty * 8 + i;
        float4 v;
        float t0 = acc[i][0], t1 = acc[i][1], t2 = acc[i][2], t3 = acc[i][3];
        v.x = t0 > 0.f ? t0 : expm1f(t0);
        v.y = t1 > 0.f ? t1 : expm1f(t1);
        v.z = t2 > 0.f ? t2 : expm1f(t2);
        v.w = t3 > 0.f ? t3 : expm1f(t3);
        *(float4*)(g_feat + (size_t)(b * Nn + r) * (H * E) + h * E + colBase + tx * 4) = v;
    }
}

// ============================================================
// K5: out (8192x64) = feat (8192x1024) @ W_act (1024x64) + b_act
// tile 64x64x16, 256 threads, 4x4 per thread; grid (1, 128)
// ============================================================
__global__ void final_gemm(const float* __restrict__ W_act,
                           const float* __restrict__ b_act,
                           float* __restrict__ out) {
    const int BM = 64, BK = 16;
    __shared__ float As[BK][BM];
    __shared__ float Bs[BK][A_];
    int rowBase = blockIdx.y * BM;
    int tid = threadIdx.x;
    int tx = tid & 15, ty = tid >> 4;
    float acc[4][4] = {};
    for (int k0 = 0; k0 < H * E; k0 += BK) {
        {
            int r = tid >> 2, c4 = tid & 3;
            float4 v = *(const float4*)(g_feat + (size_t)(rowBase + r) * (H * E) + k0 + c4 * 4);
            As[c4 * 4 + 0][r] = v.x;
            As[c4 * 4 + 1][r] = v.y;
            As[c4 * 4 + 2][r] = v.z;
            As[c4 * 4 + 3][r] = v.w;
        }
        {
            int r = tid >> 4, c4 = tid & 15;
            float4 v = *(const float4*)(W_act + (size_t)(k0 + r) * A_ + c4 * 4);
            *(float4*)&Bs[r][c4 * 4] = v;
        }
        __syncthreads();
#pragma unroll
        for (int kk = 0; kk < BK; kk++) {
            float a[4], b[4];
#pragma unroll
            for (int i = 0; i < 4; i++) a[i] = As[kk][ty * 4 + i];
            float4 bv = *(float4*)&Bs[kk][tx * 4];
            b[0] = bv.x; b[1] = bv.y; b[2] = bv.z; b[3] = bv.w;
#pragma unroll
            for (int i = 0; i < 4; i++)
#pragma unroll
                for (int j = 0; j < 4; j++) acc[i][j] += a[i] * b[j];
        }
        __syncthreads();
    }
#pragma unroll
    for (int i = 0; i < 4; i++) {
        int r = rowBase + ty * 4 + i;
        float4 bias = *(const float4*)(b_act + tx * 4);
        float4 v = make_float4(acc[i][0] + bias.x, acc[i][1] + bias.y,
                               acc[i][2] + bias.z, acc[i][3] + bias.w);
        *(float4*)(out + (size_t)r * A_ + tx * 4) = v;
    }
}

extern "C" void kernel_launch(void* const* d_in, const int* in_sizes, int n_in,
                              void* d_out, int out_size) {
    const float* x     = (const float*)d_in[0];
    const int*   adj   = (const int*)d_in[1];
    const float* W     = (const float*)d_in[2];
    const float* a1    = (const float*)d_in[3];
    const float* a2    = (const float*)d_in[4];
    const float* W_act = (const float*)d_in[5];
    const float* b_act = (const float*)d_in[6];
    float* out = (float*)d_out;

    wh_gemm<<<dim3(E / 64, BN_ROWS / 128, H), 256>>>(x, W);
    compute_f<<<H * BN_ROWS, 256>>>(a1, a2);
    softmax_att<<<dim3(Nn, Bb, H), 256>>>(adj);
    att_gemm<<<dim3(E / 64, Nn / 128, H * Bb), 256>>>();
    final_gemm<<<dim3(1, BN_ROWS / 64), 256>>>(W_act, b_act, out);
}